// round 1
// baseline (speedup 1.0000x reference)
#include <cuda_runtime.h>
#include <cuda_bf16.h>
#include <math.h>

// Problem constants
#define BB 2
#define TT 2048
#define SS 2048
#define DD 1024
#define HH 16
#define DKK 64
#define MROWS (BB * TT)          // 4096
#define HD (HH * DKK)            // 1024

// Scratch (device globals; no allocation allowed)
__device__ float g_q[MROWS * HD];
__device__ float g_k[MROWS * HD];
__device__ float g_v[MROWS * HD];
__device__ float g_attn[MROWS * HD];

// ---------------------------------------------------------------------------
// SGEMM: C[M,N] = (A[M,K] @ B[K,N] + bias[N]) * scale
// Row-major. 128x128 tile, BK=8, 256 threads, 8x8 per thread.
// ---------------------------------------------------------------------------
__global__ __launch_bounds__(256) void sgemm_bias_kernel(
    const float* __restrict__ A, const float* __restrict__ B,
    const float* __restrict__ bias, float* __restrict__ C,
    int M, int N, int K, float scale)
{
    __shared__ float As[8][128];
    __shared__ float Bs[8][128];

    const int t  = threadIdx.x;
    const int tx = t & 15;       // 0..15
    const int ty = t >> 4;       // 0..15
    const int bm = blockIdx.y * 128;
    const int bn = blockIdx.x * 128;

    float acc[8][8];
#pragma unroll
    for (int i = 0; i < 8; i++)
#pragma unroll
        for (int j = 0; j < 8; j++) acc[i][j] = 0.0f;

    // A tile load mapping: 128 rows x 8 cols -> 256 threads x float4
    const int arow = t >> 1;            // 0..127
    const int acol = (t & 1) * 4;       // 0 or 4
    // B tile load mapping: 8 rows x 128 cols -> 256 threads x float4
    const int brow = t >> 5;            // 0..7
    const int bcol = (t & 31) * 4;      // 0..124

    const float* Aptr = A + (size_t)(bm + arow) * K + acol;
    const float* Bptr = B + (size_t)brow * N + bn + bcol;

    for (int k0 = 0; k0 < K; k0 += 8) {
        float4 av = *(const float4*)(Aptr + k0);
        float4 bv = *(const float4*)(Bptr + (size_t)k0 * N);
        As[acol + 0][arow] = av.x;
        As[acol + 1][arow] = av.y;
        As[acol + 2][arow] = av.z;
        As[acol + 3][arow] = av.w;
        *(float4*)&Bs[brow][bcol] = bv;
        __syncthreads();

#pragma unroll
        for (int kk = 0; kk < 8; kk++) {
            float a[8], b[8];
            *(float4*)&a[0] = *(const float4*)&As[kk][ty * 8];
            *(float4*)&a[4] = *(const float4*)&As[kk][ty * 8 + 4];
            *(float4*)&b[0] = *(const float4*)&Bs[kk][tx * 8];
            *(float4*)&b[4] = *(const float4*)&Bs[kk][tx * 8 + 4];
#pragma unroll
            for (int i = 0; i < 8; i++)
#pragma unroll
                for (int j = 0; j < 8; j++)
                    acc[i][j] = fmaf(a[i], b[j], acc[i][j]);
        }
        __syncthreads();
    }

    // Epilogue: (acc + bias) * scale
    float bvals[8];
#pragma unroll
    for (int j = 0; j < 8; j++) bvals[j] = bias[bn + tx * 8 + j];

#pragma unroll
    for (int i = 0; i < 8; i++) {
        const int row = bm + ty * 8 + i;
        float* crow = C + (size_t)row * N + bn + tx * 8;
        float4 o0, o1;
        o0.x = (acc[i][0] + bvals[0]) * scale;
        o0.y = (acc[i][1] + bvals[1]) * scale;
        o0.z = (acc[i][2] + bvals[2]) * scale;
        o0.w = (acc[i][3] + bvals[3]) * scale;
        o1.x = (acc[i][4] + bvals[4]) * scale;
        o1.y = (acc[i][5] + bvals[5]) * scale;
        o1.z = (acc[i][6] + bvals[6]) * scale;
        o1.w = (acc[i][7] + bvals[7]) * scale;
        *(float4*)(crow)     = o0;
        *(float4*)(crow + 4) = o1;
    }
}

// ---------------------------------------------------------------------------
// Flash attention: per (b, h, t-block of 64). DK=64, S tiles of 64.
// Layouts: q/k/v/attn are [b][t][h][dk] flattened with row stride HD=1024.
// 256 threads: tx in [0,16) -> 4 cols/dims, ty in [0,16) -> 4 rows.
// ---------------------------------------------------------------------------
__global__ __launch_bounds__(256) void flash_attn_kernel(
    const float* __restrict__ Qg, const float* __restrict__ Kg,
    const float* __restrict__ Vg, float* __restrict__ Og)
{
    __shared__ float Qs[64 * 64];   // [r][k]
    __shared__ float KPs[64 * 64];  // K transposed [k][c]; reused as P [r][c]
    __shared__ float Vs[64 * 64];   // [c][d]

    const int t  = threadIdx.x;
    const int tx = t & 15;
    const int ty = t >> 4;
    const int tb = blockIdx.x;     // t block (0..31)
    const int h  = blockIdx.y;     // head
    const int b  = blockIdx.z;     // batch

    const size_t base_q  = ((size_t)(b * TT + tb * 64) * HH + h) * DKK;
    const size_t base_kv = ((size_t)(b * SS) * HH + h) * DKK;

    // Load Q tile [64 rows][64 k]
    for (int i = t; i < 1024; i += 256) {
        const int r  = i >> 4;
        const int k4 = (i & 15) << 2;
        *(float4*)&Qs[r * 64 + k4] =
            *(const float4*)&Qg[base_q + (size_t)r * HD + k4];
    }

    const int r0 = ty * 4;
    const int c0 = tx * 4;

    float m[4], l[4], o[4][4];
#pragma unroll
    for (int i = 0; i < 4; i++) {
        m[i] = -1e30f;
        l[i] = 0.0f;
#pragma unroll
        for (int j = 0; j < 4; j++) o[i][j] = 0.0f;
    }

    for (int sb = 0; sb < SS / 64; sb++) {
        // Load K (transposed into KPs) and V
        for (int i = t; i < 1024; i += 256) {
            const int c  = i >> 4;
            const int k4 = (i & 15) << 2;
            const size_t goff = base_kv + (size_t)(sb * 64 + c) * HD + k4;
            float4 kv = *(const float4*)&Kg[goff];
            KPs[(k4 + 0) * 64 + c] = kv.x;
            KPs[(k4 + 1) * 64 + c] = kv.y;
            KPs[(k4 + 2) * 64 + c] = kv.z;
            KPs[(k4 + 3) * 64 + c] = kv.w;
            *(float4*)&Vs[c * 64 + k4] = *(const float4*)&Vg[goff];
        }
        __syncthreads();

        // Scores: s[i][j] = sum_k Q[r0+i][k] * K[c0+j][k]
        float s[4][4];
#pragma unroll
        for (int i = 0; i < 4; i++)
#pragma unroll
            for (int j = 0; j < 4; j++) s[i][j] = 0.0f;

#pragma unroll 8
        for (int k = 0; k < 64; k++) {
            float4 bv = *(const float4*)&KPs[k * 64 + c0];
            const float bj[4] = {bv.x, bv.y, bv.z, bv.w};
#pragma unroll
            for (int i = 0; i < 4; i++) {
                const float a = Qs[(r0 + i) * 64 + k];
#pragma unroll
                for (int j = 0; j < 4; j++)
                    s[i][j] = fmaf(a, bj[j], s[i][j]);
            }
        }
        __syncthreads();  // all reads of KPs done before P overwrite

        // Online softmax update + write P into KPs
#pragma unroll
        for (int i = 0; i < 4; i++) {
            float bm = fmaxf(fmaxf(s[i][0], s[i][1]), fmaxf(s[i][2], s[i][3]));
#pragma unroll
            for (int w = 1; w < 16; w <<= 1)
                bm = fmaxf(bm, __shfl_xor_sync(0xffffffffu, bm, w));
            const float mn = fmaxf(m[i], bm);
            const float alpha = __expf(m[i] - mn);
            float p0 = __expf(s[i][0] - mn);
            float p1 = __expf(s[i][1] - mn);
            float p2 = __expf(s[i][2] - mn);
            float p3 = __expf(s[i][3] - mn);
            float ps = p0 + p1 + p2 + p3;
#pragma unroll
            for (int w = 1; w < 16; w <<= 1)
                ps += __shfl_xor_sync(0xffffffffu, ps, w);
            l[i] = l[i] * alpha + ps;
            m[i] = mn;
#pragma unroll
            for (int j = 0; j < 4; j++) o[i][j] *= alpha;
            *(float4*)&KPs[(r0 + i) * 64 + c0] = make_float4(p0, p1, p2, p3);
        }
        __syncthreads();  // P fully written

        // O update: o[i][j] += sum_c P[r0+i][c] * V[c][c0+j]
#pragma unroll 8
        for (int c = 0; c < 64; c++) {
            float4 vv = *(const float4*)&Vs[c * 64 + c0];
#pragma unroll
            for (int i = 0; i < 4; i++) {
                const float pi = KPs[(r0 + i) * 64 + c];
                o[i][0] = fmaf(pi, vv.x, o[i][0]);
                o[i][1] = fmaf(pi, vv.y, o[i][1]);
                o[i][2] = fmaf(pi, vv.z, o[i][2]);
                o[i][3] = fmaf(pi, vv.w, o[i][3]);
            }
        }
        __syncthreads();  // Vs/KPs reads done before next tile load
    }

    // Normalize and store
#pragma unroll
    for (int i = 0; i < 4; i++) {
        const float inv = 1.0f / l[i];
        float4 ov = make_float4(o[i][0] * inv, o[i][1] * inv,
                                o[i][2] * inv, o[i][3] * inv);
        *(float4*)&Og[base_q + (size_t)(r0 + i) * HD + c0] = ov;
    }
}

// ---------------------------------------------------------------------------
// Launch
// ---------------------------------------------------------------------------
extern "C" void kernel_launch(void* const* d_in, const int* in_sizes, int n_in,
                              void* d_out, int out_size)
{
    // metadata order: query, value, key, Wq, bq, Wk, bk, Wv, bv, Wo, bo
    const float* query = (const float*)d_in[0];
    const float* value = (const float*)d_in[1];
    const float* key   = (const float*)d_in[2];
    const float* Wq    = (const float*)d_in[3];
    const float* bq    = (const float*)d_in[4];
    const float* Wk    = (const float*)d_in[5];
    const float* bk    = (const float*)d_in[6];
    const float* Wv    = (const float*)d_in[7];
    const float* bv    = (const float*)d_in[8];
    const float* Wo    = (const float*)d_in[9];
    const float* bo    = (const float*)d_in[10];
    float* out = (float*)d_out;

    float *q, *k, *v, *attn;
    cudaGetSymbolAddress((void**)&q,    g_q);
    cudaGetSymbolAddress((void**)&k,    g_k);
    cudaGetSymbolAddress((void**)&v,    g_v);
    cudaGetSymbolAddress((void**)&attn, g_attn);

    const dim3 gemm_grid(HD / 128, MROWS / 128);  // (8, 32)
    const float qscale = 0.125f;                  // 1/sqrt(DK)

    // Projections
    sgemm_bias_kernel<<<gemm_grid, 256>>>(query, Wq, bq, q, MROWS, HD, DD, qscale);
    sgemm_bias_kernel<<<gemm_grid, 256>>>(key,   Wk, bk, k, MROWS, HD, DD, 1.0f);
    sgemm_bias_kernel<<<gemm_grid, 256>>>(value, Wv, bv, v, MROWS, HD, DD, 1.0f);

    // Attention
    flash_attn_kernel<<<dim3(TT / 64, HH, BB), 256>>>(q, k, v, attn);

    // Output projection
    sgemm_bias_kernel<<<gemm_grid, 256>>>(attn, Wo, bo, out, MROWS, DD, HD, 1.0f);
}

// round 2
// speedup vs baseline: 5.4954x; 5.4954x over previous
#include <cuda_runtime.h>
#include <cuda_fp16.h>
#include <math.h>

#define BB 2
#define TT 2048
#define SS 2048
#define DD 1024
#define HH 16
#define DKK 64
#define MROWS (BB * TT)          // 4096
#define HD (HH * DKK)            // 1024

// fp16 scratch (device globals; no allocation allowed)
__device__ __half g_xq[MROWS * DD];
__device__ __half g_xk[MROWS * DD];
__device__ __half g_xv[MROWS * DD];
__device__ __half g_wq[DD * HD];
__device__ __half g_wk[DD * HD];
__device__ __half g_wv[DD * HD];
__device__ __half g_wo[HD * DD];
__device__ __half g_q[MROWS * HD];
__device__ __half g_k[MROWS * HD];
__device__ __half g_v[MROWS * HD];
__device__ __half g_attn[MROWS * HD];

// ---------------------------------------------------------------------------
// Helpers
// ---------------------------------------------------------------------------
__device__ __forceinline__ unsigned sptr(const void* p) {
    return (unsigned)__cvta_generic_to_shared(p);
}

__device__ __forceinline__ void ldm_x4(unsigned a, unsigned& r0, unsigned& r1,
                                       unsigned& r2, unsigned& r3) {
    asm volatile("ldmatrix.sync.aligned.m8n8.x4.shared.b16 {%0,%1,%2,%3}, [%4];\n"
                 : "=r"(r0), "=r"(r1), "=r"(r2), "=r"(r3) : "r"(a));
}

__device__ __forceinline__ void ldm_x4_t(unsigned a, unsigned& r0, unsigned& r1,
                                         unsigned& r2, unsigned& r3) {
    asm volatile("ldmatrix.sync.aligned.m8n8.x4.trans.shared.b16 {%0,%1,%2,%3}, [%4];\n"
                 : "=r"(r0), "=r"(r1), "=r"(r2), "=r"(r3) : "r"(a));
}

__device__ __forceinline__ void mma16816(float* c, const unsigned* a, const unsigned* b) {
    asm volatile(
        "mma.sync.aligned.m16n8k16.row.col.f32.f16.f16.f32 "
        "{%0,%1,%2,%3},{%4,%5,%6,%7},{%8,%9},{%0,%1,%2,%3};\n"
        : "+f"(c[0]), "+f"(c[1]), "+f"(c[2]), "+f"(c[3])
        : "r"(a[0]), "r"(a[1]), "r"(a[2]), "r"(a[3]), "r"(b[0]), "r"(b[1]));
}

#define CP16(dst, src) \
    asm volatile("cp.async.cg.shared.global [%0], [%1], 16;\n" :: "r"(dst), "l"(src))
#define CP_COMMIT() asm volatile("cp.async.commit_group;\n")
#define CP_WAIT1()  asm volatile("cp.async.wait_group 1;\n")
#define CP_WAIT0()  asm volatile("cp.async.wait_group 0;\n")

__device__ __forceinline__ unsigned pack2(float x, float y) {
    __half2 h = __floats2half2_rn(x, y);
    return *(unsigned*)&h;
}

// ---------------------------------------------------------------------------
// f32 -> f16 conversion
// ---------------------------------------------------------------------------
__global__ __launch_bounds__(256) void f2h_kernel(const float* __restrict__ in,
                                                  __half* __restrict__ out, int n) {
    int i = (blockIdx.x * blockDim.x + threadIdx.x) * 4;
    if (i < n) {
        float4 v = *(const float4*)(in + i);
        __half2* o = (__half2*)(out + i);
        o[0] = __floats2half2_rn(v.x, v.y);
        o[1] = __floats2half2_rn(v.z, v.w);
    }
}

// ---------------------------------------------------------------------------
// HGEMM: C[M,N] = (A[M,K]@B[K,N] + bias[N]) * scale; fp16 in, fp32 accum.
// 128x128x32 tile, 256 threads (8 warps, 64x32 warp tile), cp.async 2-stage.
// ---------------------------------------------------------------------------
template <bool HALF_OUT>
__global__ __launch_bounds__(256) void hgemm_bias(
    const __half* __restrict__ A, const __half* __restrict__ B,
    const float* __restrict__ bias, void* __restrict__ Cout,
    int M, int N, int K, float scale)
{
    constexpr int BM = 128, BN = 128, BK = 32;
    __shared__ __half As[2][BM][BK + 8];
    __shared__ __half Bs[2][BK][BN + 8];

    const int t = threadIdx.x, lane = t & 31, wid = t >> 5;
    const int wr = wid >> 2, wc = wid & 3;   // 2x4 warp grid
    const int bm = blockIdx.y * BM, bn = blockIdx.x * BN;
    const int mw = wr * 64, nw = wc * 32;

    float acc[4][4][4];
#pragma unroll
    for (int i = 0; i < 4; i++)
#pragma unroll
        for (int j = 0; j < 4; j++)
#pragma unroll
            for (int r = 0; r < 4; r++) acc[i][j][r] = 0.0f;

    // load mappings
    const int arow = t >> 1, ac8 = (t & 1) * 16;  // A: 2 uint4 per thread
    const int bv0 = t * 2;                        // B: 2 vectors per thread
    const __half* Ag = A + (size_t)(bm + arow) * K + ac8;

    auto load_tile = [&](int buf, int it) {
        const int k0 = it * BK;
        unsigned da = sptr(&As[buf][arow][ac8]);
        CP16(da, Ag + k0);
        CP16(da + 16, Ag + k0 + 8);
#pragma unroll
        for (int i = 0; i < 2; i++) {
            const int v = bv0 + i;
            const int br = v >> 4, bc8 = (v & 15) * 8;
            CP16(sptr(&Bs[buf][br][bc8]),
                 B + (size_t)(k0 + br) * N + bn + bc8);
        }
    };

    const int NK = K / BK;
    int buf = 0;
    load_tile(0, 0);
    CP_COMMIT();

    for (int it = 0; it < NK; it++) {
        if (it + 1 < NK) {
            load_tile(buf ^ 1, it + 1);
            CP_COMMIT();
            CP_WAIT1();
        } else {
            CP_WAIT0();
        }
        __syncthreads();

#pragma unroll
        for (int kk = 0; kk < 2; kk++) {
            const int k0 = kk * 16;
            unsigned afr[4][4];
#pragma unroll
            for (int i = 0; i < 4; i++)
                ldm_x4(sptr(&As[buf][mw + i * 16 + (lane & 15)][k0 + (lane >> 4) * 8]),
                       afr[i][0], afr[i][1], afr[i][2], afr[i][3]);
            unsigned bfr[4][2];
#pragma unroll
            for (int jp = 0; jp < 2; jp++) {
                unsigned r0, r1, r2, r3;
                ldm_x4_t(sptr(&Bs[buf][k0 + (lane & 15)][nw + jp * 16 + (lane >> 4) * 8]),
                         r0, r1, r2, r3);
                bfr[2 * jp][0] = r0; bfr[2 * jp][1] = r1;
                bfr[2 * jp + 1][0] = r2; bfr[2 * jp + 1][1] = r3;
            }
#pragma unroll
            for (int i = 0; i < 4; i++)
#pragma unroll
                for (int j = 0; j < 4; j++)
                    mma16816(acc[i][j], afr[i], bfr[j]);
        }
        __syncthreads();
        buf ^= 1;
    }

    // Epilogue
#pragma unroll
    for (int i = 0; i < 4; i++) {
#pragma unroll
        for (int j = 0; j < 4; j++) {
            const int col = bn + nw + j * 8 + (lane & 3) * 2;
            const float b0 = bias[col], b1 = bias[col + 1];
            const int row_lo = bm + mw + i * 16 + (lane >> 2);
            const int row_hi = row_lo + 8;
            const float v0 = (acc[i][j][0] + b0) * scale;
            const float v1 = (acc[i][j][1] + b1) * scale;
            const float v2 = (acc[i][j][2] + b0) * scale;
            const float v3 = (acc[i][j][3] + b1) * scale;
            if (HALF_OUT) {
                __half* C = (__half*)Cout;
                *(__half2*)(C + (size_t)row_lo * N + col) = __floats2half2_rn(v0, v1);
                *(__half2*)(C + (size_t)row_hi * N + col) = __floats2half2_rn(v2, v3);
            } else {
                float* C = (float*)Cout;
                *(float2*)(C + (size_t)row_lo * N + col) = make_float2(v0, v1);
                *(float2*)(C + (size_t)row_hi * N + col) = make_float2(v2, v3);
            }
        }
    }
}

// ---------------------------------------------------------------------------
// Flash attention with mma. Per (b, h, 64-row Q tile); 4 warps x 16 rows.
// Q/K/V fp16 [b][t][h][dk] layout (row stride HD). Softmax fp32. P in regs.
// ---------------------------------------------------------------------------
__global__ __launch_bounds__(128) void flash_mma(
    const __half* __restrict__ Q, const __half* __restrict__ K,
    const __half* __restrict__ V, __half* __restrict__ O)
{
    __shared__ __half Ks[64][72];
    __shared__ __half Vs[64][72];

    const int t = threadIdx.x, lane = t & 31, wid = t >> 5;
    const int tb = blockIdx.x, h = blockIdx.y, b = blockIdx.z;
    const size_t base_q = ((size_t)(b * TT + tb * 64) * HH + h) * DKK;
    const size_t base_kv = ((size_t)(b * SS) * HH + h) * DKK;
    const int mw = wid * 16;

    // Stage Q through Ks, grab A-fragments into registers
    for (int v = t; v < 512; v += 128) {
        const int r = v >> 3, c8 = (v & 7) * 8;
        *(uint4*)&Ks[r][c8] = *(const uint4*)&Q[base_q + (size_t)r * HD + c8];
    }
    __syncthreads();
    unsigned qf[4][4];
#pragma unroll
    for (int kk = 0; kk < 4; kk++)
        ldm_x4(sptr(&Ks[mw + (lane & 15)][kk * 16 + (lane >> 4) * 8]),
               qf[kk][0], qf[kk][1], qf[kk][2], qf[kk][3]);
    __syncthreads();

    float o[8][4];
#pragma unroll
    for (int j = 0; j < 8; j++)
#pragma unroll
        for (int r = 0; r < 4; r++) o[j][r] = 0.0f;
    float m_lo = -1e30f, m_hi = -1e30f, l_lo = 0.0f, l_hi = 0.0f;

    for (int sb = 0; sb < SS / 64; sb++) {
        const size_t kvoff = base_kv + (size_t)(sb * 64) * HD;
        for (int v = t; v < 512; v += 128) {
            const int r = v >> 3, c8 = (v & 7) * 8;
            const size_t g = kvoff + (size_t)r * HD + c8;
            *(uint4*)&Ks[r][c8] = *(const uint4*)&K[g];
            *(uint4*)&Vs[r][c8] = *(const uint4*)&V[g];
        }
        __syncthreads();

        // Scores S = Q @ K^T : B from Ks[n][k] via non-trans ldmatrix
        float s[8][4];
#pragma unroll
        for (int j = 0; j < 8; j++)
#pragma unroll
            for (int r = 0; r < 4; r++) s[j][r] = 0.0f;

#pragma unroll
        for (int kk = 0; kk < 4; kk++) {
            unsigned bf[8][2];
#pragma unroll
            for (int np = 0; np < 4; np++) {
                unsigned r0, r1, r2, r3;
                const int nrow = np * 16 + (lane & 7) + ((lane >> 4) << 3);
                const int kcol = kk * 16 + ((lane >> 3) & 1) * 8;
                ldm_x4(sptr(&Ks[nrow][kcol]), r0, r1, r2, r3);
                bf[2 * np][0] = r0; bf[2 * np][1] = r1;
                bf[2 * np + 1][0] = r2; bf[2 * np + 1][1] = r3;
            }
#pragma unroll
            for (int j = 0; j < 8; j++)
                mma16816(s[j], qf[kk], bf[j]);
        }

        // Online softmax (rows lane>>2 and +8)
        float mx_lo = -1e30f, mx_hi = -1e30f;
#pragma unroll
        for (int j = 0; j < 8; j++) {
            mx_lo = fmaxf(mx_lo, fmaxf(s[j][0], s[j][1]));
            mx_hi = fmaxf(mx_hi, fmaxf(s[j][2], s[j][3]));
        }
        mx_lo = fmaxf(mx_lo, __shfl_xor_sync(0xffffffffu, mx_lo, 1));
        mx_lo = fmaxf(mx_lo, __shfl_xor_sync(0xffffffffu, mx_lo, 2));
        mx_hi = fmaxf(mx_hi, __shfl_xor_sync(0xffffffffu, mx_hi, 1));
        mx_hi = fmaxf(mx_hi, __shfl_xor_sync(0xffffffffu, mx_hi, 2));

        const float mn_lo = fmaxf(m_lo, mx_lo);
        const float mn_hi = fmaxf(m_hi, mx_hi);
        const float a_lo = __expf(m_lo - mn_lo);
        const float a_hi = __expf(m_hi - mn_hi);
        m_lo = mn_lo; m_hi = mn_hi;

        float sum_lo = 0.0f, sum_hi = 0.0f;
#pragma unroll
        for (int j = 0; j < 8; j++) {
            s[j][0] = __expf(s[j][0] - mn_lo);
            s[j][1] = __expf(s[j][1] - mn_lo);
            s[j][2] = __expf(s[j][2] - mn_hi);
            s[j][3] = __expf(s[j][3] - mn_hi);
            sum_lo += s[j][0] + s[j][1];
            sum_hi += s[j][2] + s[j][3];
        }
        sum_lo += __shfl_xor_sync(0xffffffffu, sum_lo, 1);
        sum_lo += __shfl_xor_sync(0xffffffffu, sum_lo, 2);
        sum_hi += __shfl_xor_sync(0xffffffffu, sum_hi, 1);
        sum_hi += __shfl_xor_sync(0xffffffffu, sum_hi, 2);
        l_lo = l_lo * a_lo + sum_lo;
        l_hi = l_hi * a_hi + sum_hi;

#pragma unroll
        for (int j = 0; j < 8; j++) {
            o[j][0] *= a_lo; o[j][1] *= a_lo;
            o[j][2] *= a_hi; o[j][3] *= a_hi;
        }

        // P fp16 A-fragments (C-layout == A-layout identity)
        unsigned pa[4][4];
#pragma unroll
        for (int kk = 0; kk < 4; kk++) {
            pa[kk][0] = pack2(s[2 * kk][0], s[2 * kk][1]);
            pa[kk][1] = pack2(s[2 * kk][2], s[2 * kk][3]);
            pa[kk][2] = pack2(s[2 * kk + 1][0], s[2 * kk + 1][1]);
            pa[kk][3] = pack2(s[2 * kk + 1][2], s[2 * kk + 1][3]);
        }

        // O += P @ V : B from Vs[k][n] via trans ldmatrix
#pragma unroll
        for (int kk = 0; kk < 4; kk++) {
            unsigned vb[8][2];
#pragma unroll
            for (int np = 0; np < 4; np++) {
                unsigned r0, r1, r2, r3;
                ldm_x4_t(sptr(&Vs[kk * 16 + (lane & 15)][np * 16 + (lane >> 4) * 8]),
                         r0, r1, r2, r3);
                vb[2 * np][0] = r0; vb[2 * np][1] = r1;
                vb[2 * np + 1][0] = r2; vb[2 * np + 1][1] = r3;
            }
#pragma unroll
            for (int j = 0; j < 8; j++)
                mma16816(o[j], pa[kk], vb[j]);
        }
        __syncthreads();
    }

    // Normalize + store fp16
    const float inv_lo = 1.0f / l_lo, inv_hi = 1.0f / l_hi;
    const int row_lo = mw + (lane >> 2);
    const int row_hi = row_lo + 8;
#pragma unroll
    for (int j = 0; j < 8; j++) {
        const int col = j * 8 + (lane & 3) * 2;
        *(__half2*)&O[base_q + (size_t)row_lo * HD + col] =
            __floats2half2_rn(o[j][0] * inv_lo, o[j][1] * inv_lo);
        *(__half2*)&O[base_q + (size_t)row_hi * HD + col] =
            __floats2half2_rn(o[j][2] * inv_hi, o[j][3] * inv_hi);
    }
}

// ---------------------------------------------------------------------------
// Launch
// ---------------------------------------------------------------------------
extern "C" void kernel_launch(void* const* d_in, const int* in_sizes, int n_in,
                              void* d_out, int out_size)
{
    const float* query = (const float*)d_in[0];
    const float* value = (const float*)d_in[1];
    const float* key   = (const float*)d_in[2];
    const float* Wq    = (const float*)d_in[3];
    const float* bq    = (const float*)d_in[4];
    const float* Wk    = (const float*)d_in[5];
    const float* bk    = (const float*)d_in[6];
    const float* Wv    = (const float*)d_in[7];
    const float* bv    = (const float*)d_in[8];
    const float* Wo    = (const float*)d_in[9];
    const float* bo    = (const float*)d_in[10];
    float* out = (float*)d_out;

    __half *xq, *xk, *xv, *wq, *wk, *wv, *wo, *q, *k, *v, *attn;
    cudaGetSymbolAddress((void**)&xq, g_xq);
    cudaGetSymbolAddress((void**)&xk, g_xk);
    cudaGetSymbolAddress((void**)&xv, g_xv);
    cudaGetSymbolAddress((void**)&wq, g_wq);
    cudaGetSymbolAddress((void**)&wk, g_wk);
    cudaGetSymbolAddress((void**)&wv, g_wv);
    cudaGetSymbolAddress((void**)&wo, g_wo);
    cudaGetSymbolAddress((void**)&q,  g_q);
    cudaGetSymbolAddress((void**)&k,  g_k);
    cudaGetSymbolAddress((void**)&v,  g_v);
    cudaGetSymbolAddress((void**)&attn, g_attn);

    const int nbig = MROWS * DD;    // 4M
    const int nw   = DD * HD;       // 1M
    f2h_kernel<<<nbig / 1024, 256>>>(query, xq, nbig);
    f2h_kernel<<<nbig / 1024, 256>>>(key,   xk, nbig);
    f2h_kernel<<<nbig / 1024, 256>>>(value, xv, nbig);
    f2h_kernel<<<nw / 1024, 256>>>(Wq, wq, nw);
    f2h_kernel<<<nw / 1024, 256>>>(Wk, wk, nw);
    f2h_kernel<<<nw / 1024, 256>>>(Wv, wv, nw);
    f2h_kernel<<<nw / 1024, 256>>>(Wo, wo, nw);

    const dim3 gg(HD / 128, MROWS / 128);  // (8, 32)
    hgemm_bias<true><<<gg, 256>>>(xq, wq, bq, q, MROWS, HD, DD, 0.125f);
    hgemm_bias<true><<<gg, 256>>>(xk, wk, bk, k, MROWS, HD, DD, 1.0f);
    hgemm_bias<true><<<gg, 256>>>(xv, wv, bv, v, MROWS, HD, DD, 1.0f);

    flash_mma<<<dim3(TT / 64, HH, BB), 128>>>(q, k, v, attn);

    hgemm_bias<false><<<gg, 256>>>(attn, wo, bo, out, MROWS, DD, HD, 1.0f);
}

// round 3
// speedup vs baseline: 6.9106x; 1.2575x over previous
#include <cuda_runtime.h>
#include <cuda_fp16.h>

#define BB 2
#define TT 2048
#define SS 2048
#define DD 1024
#define HH 16
#define DKK 64
#define MROWS (BB * TT)          // 4096
#define HD (HH * DKK)            // 1024

// fp16 scratch (device globals; no allocation allowed)
__device__ __half g_xq[MROWS * DD];
__device__ __half g_xk[MROWS * DD];
__device__ __half g_xv[MROWS * DD];
__device__ __half g_wq[DD * HD];
__device__ __half g_wk[DD * HD];
__device__ __half g_wv[DD * HD];
__device__ __half g_wo[HD * DD];
__device__ __half g_q[MROWS * HD];
__device__ __half g_k[MROWS * HD];
__device__ __half g_v[MROWS * HD];
__device__ __half g_attn[MROWS * HD];

// ---------------------------------------------------------------------------
// Helpers
// ---------------------------------------------------------------------------
__device__ __forceinline__ unsigned sptr(const void* p) {
    return (unsigned)__cvta_generic_to_shared(p);
}
__device__ __forceinline__ void ldm_x4(unsigned a, unsigned& r0, unsigned& r1,
                                       unsigned& r2, unsigned& r3) {
    asm volatile("ldmatrix.sync.aligned.m8n8.x4.shared.b16 {%0,%1,%2,%3}, [%4];\n"
                 : "=r"(r0), "=r"(r1), "=r"(r2), "=r"(r3) : "r"(a));
}
__device__ __forceinline__ void ldm_x4_t(unsigned a, unsigned& r0, unsigned& r1,
                                         unsigned& r2, unsigned& r3) {
    asm volatile("ldmatrix.sync.aligned.m8n8.x4.trans.shared.b16 {%0,%1,%2,%3}, [%4];\n"
                 : "=r"(r0), "=r"(r1), "=r"(r2), "=r"(r3) : "r"(a));
}
__device__ __forceinline__ void mma16816(float* c, const unsigned* a, const unsigned* b) {
    asm volatile(
        "mma.sync.aligned.m16n8k16.row.col.f32.f16.f16.f32 "
        "{%0,%1,%2,%3},{%4,%5,%6,%7},{%8,%9},{%0,%1,%2,%3};\n"
        : "+f"(c[0]), "+f"(c[1]), "+f"(c[2]), "+f"(c[3])
        : "r"(a[0]), "r"(a[1]), "r"(a[2]), "r"(a[3]), "r"(b[0]), "r"(b[1]));
}
#define CP16(dst, src) \
    asm volatile("cp.async.cg.shared.global [%0], [%1], 16;\n" :: "r"(dst), "l"(src))
#define CP_COMMIT() asm volatile("cp.async.commit_group;\n")
#define CP_WAIT0()  asm volatile("cp.async.wait_group 0;\n")

__device__ __forceinline__ unsigned pack2(float x, float y) {
    __half2 h = __floats2half2_rn(x, y);
    return *(unsigned*)&h;
}
__device__ __forceinline__ unsigned ex2h2(unsigned x) {
    unsigned r;
    asm("ex2.approx.f16x2 %0, %1;\n" : "=r"(r) : "r"(x));
    return r;
}
__device__ __forceinline__ float ex2f(float x) {
    float r;
    asm("ex2.approx.f32 %0, %1;\n" : "=f"(r) : "f"(x));
    return r;
}

// ---------------------------------------------------------------------------
// Batched f32 -> f16 conversions (8 elems/thread)
// ---------------------------------------------------------------------------
__global__ __launch_bounds__(256) void f2h_inputs(
    const float* __restrict__ a, const float* __restrict__ b,
    const float* __restrict__ c, __half* __restrict__ oa,
    __half* __restrict__ ob, __half* __restrict__ oc)
{
    const float* src[3] = {a, b, c};
    __half* dst[3] = {oa, ob, oc};
    const int z = blockIdx.y;
    const int i = (blockIdx.x * 256 + threadIdx.x) * 8;
    float4 v0 = *(const float4*)(src[z] + i);
    float4 v1 = *(const float4*)(src[z] + i + 4);
    __half2* o = (__half2*)(dst[z] + i);
    o[0] = __floats2half2_rn(v0.x, v0.y);
    o[1] = __floats2half2_rn(v0.z, v0.w);
    o[2] = __floats2half2_rn(v1.x, v1.y);
    o[3] = __floats2half2_rn(v1.z, v1.w);
}

__global__ __launch_bounds__(256) void f2h_weights(
    const float* __restrict__ a, const float* __restrict__ b,
    const float* __restrict__ c, const float* __restrict__ d,
    __half* __restrict__ oa, __half* __restrict__ ob,
    __half* __restrict__ oc, __half* __restrict__ od)
{
    const float* src[4] = {a, b, c, d};
    __half* dst[4] = {oa, ob, oc, od};
    const int z = blockIdx.y;
    const int i = (blockIdx.x * 256 + threadIdx.x) * 8;
    float4 v0 = *(const float4*)(src[z] + i);
    float4 v1 = *(const float4*)(src[z] + i + 4);
    __half2* o = (__half2*)(dst[z] + i);
    o[0] = __floats2half2_rn(v0.x, v0.y);
    o[1] = __floats2half2_rn(v0.z, v0.w);
    o[2] = __floats2half2_rn(v1.x, v1.y);
    o[3] = __floats2half2_rn(v1.z, v1.w);
}

// ---------------------------------------------------------------------------
// HGEMM body: C[M,N] = (A[M,K]@B[K,N] + bias[N]) * scale; fp16 in, fp32 acc.
// 128x128x32 tile, 256 threads (8 warps, 64x32 warp tile).
// 2-stage cp.async, single __syncthreads per K-tile.
// ---------------------------------------------------------------------------
template <bool HALF_OUT>
__device__ __forceinline__ void hgemm_body(
    const __half* __restrict__ A, const __half* __restrict__ B,
    const float* __restrict__ bias, void* __restrict__ Cout,
    int N, int K, float scale)
{
    constexpr int BM = 128, BN = 128, BK = 32;
    __shared__ __half As[2][BM][BK + 8];
    __shared__ __half Bs[2][BK][BN + 8];

    const int t = threadIdx.x, lane = t & 31, wid = t >> 5;
    const int wr = wid >> 2, wc = wid & 3;
    const int bm = blockIdx.y * BM, bn = blockIdx.x * BN;
    const int mw = wr * 64, nw = wc * 32;

    float acc[4][4][4];
#pragma unroll
    for (int i = 0; i < 4; i++)
#pragma unroll
        for (int j = 0; j < 4; j++)
#pragma unroll
            for (int r = 0; r < 4; r++) acc[i][j][r] = 0.0f;

    const int arow = t >> 1, ac8 = (t & 1) * 16;
    const int bv0 = t * 2;
    const __half* Ag = A + (size_t)(bm + arow) * K + ac8;

    auto load_tile = [&](int buf, int it) {
        const int k0 = it * BK;
        unsigned da = sptr(&As[buf][arow][ac8]);
        CP16(da, Ag + k0);
        CP16(da + 16, Ag + k0 + 8);
#pragma unroll
        for (int i = 0; i < 2; i++) {
            const int v = bv0 + i;
            const int br = v >> 4, bc8 = (v & 15) * 8;
            CP16(sptr(&Bs[buf][br][bc8]), B + (size_t)(k0 + br) * N + bn + bc8);
        }
    };

    const int NK = K / BK;
    load_tile(0, 0);
    CP_COMMIT();

    for (int it = 0; it < NK; it++) {
        const int buf = it & 1;
        CP_WAIT0();
        __syncthreads();
        if (it + 1 < NK) {
            load_tile(buf ^ 1, it + 1);
            CP_COMMIT();
        }
#pragma unroll
        for (int kk = 0; kk < 2; kk++) {
            const int k0 = kk * 16;
            unsigned afr[4][4];
#pragma unroll
            for (int i = 0; i < 4; i++)
                ldm_x4(sptr(&As[buf][mw + i * 16 + (lane & 15)][k0 + (lane >> 4) * 8]),
                       afr[i][0], afr[i][1], afr[i][2], afr[i][3]);
            unsigned bfr[4][2];
#pragma unroll
            for (int jp = 0; jp < 2; jp++) {
                unsigned r0, r1, r2, r3;
                ldm_x4_t(sptr(&Bs[buf][k0 + (lane & 15)][nw + jp * 16 + (lane >> 4) * 8]),
                         r0, r1, r2, r3);
                bfr[2 * jp][0] = r0; bfr[2 * jp][1] = r1;
                bfr[2 * jp + 1][0] = r2; bfr[2 * jp + 1][1] = r3;
            }
#pragma unroll
            for (int i = 0; i < 4; i++)
#pragma unroll
                for (int j = 0; j < 4; j++)
                    mma16816(acc[i][j], afr[i], bfr[j]);
        }
    }

#pragma unroll
    for (int i = 0; i < 4; i++) {
#pragma unroll
        for (int j = 0; j < 4; j++) {
            const int col = bn + nw + j * 8 + (lane & 3) * 2;
            const float b0 = bias[col], b1 = bias[col + 1];
            const int row_lo = bm + mw + i * 16 + (lane >> 2);
            const int row_hi = row_lo + 8;
            const float v0 = (acc[i][j][0] + b0) * scale;
            const float v1 = (acc[i][j][1] + b1) * scale;
            const float v2 = (acc[i][j][2] + b0) * scale;
            const float v3 = (acc[i][j][3] + b1) * scale;
            if (HALF_OUT) {
                __half* C = (__half*)Cout;
                *(__half2*)(C + (size_t)row_lo * N + col) = __floats2half2_rn(v0, v1);
                *(__half2*)(C + (size_t)row_hi * N + col) = __floats2half2_rn(v2, v3);
            } else {
                float* C = (float*)Cout;
                *(float2*)(C + (size_t)row_lo * N + col) = make_float2(v0, v1);
                *(float2*)(C + (size_t)row_hi * N + col) = make_float2(v2, v3);
            }
        }
    }
}

struct ProjArgs {
    const __half* A[3];
    const __half* W[3];
    const float* bias[3];
    __half* C[3];
    float scale[3];
};

__global__ __launch_bounds__(256) void proj_gemm(ProjArgs p) {
    const int z = blockIdx.z;
    hgemm_body<true>(p.A[z], p.W[z], p.bias[z], p.C[z], HD, DD, p.scale[z]);
}

__global__ __launch_bounds__(256) void out_gemm(
    const __half* __restrict__ A, const __half* __restrict__ B,
    const float* __restrict__ bias, float* __restrict__ C) {
    hgemm_body<false>(A, B, bias, C, DD, HD, 1.0f);
}

// ---------------------------------------------------------------------------
// Flash attention, scores in log2-domain (log2e folded into q-projection).
// 128-row Q tile, 8 warps x 16 rows, 64-key S tiles, 2-stage cp.async,
// one __syncthreads per S tile. exp via ex2.approx.f16x2; row-sums via
// ones-matrix MMA.
// ---------------------------------------------------------------------------
__global__ __launch_bounds__(256) void flash_mma(
    const __half* __restrict__ Q, const __half* __restrict__ K,
    const __half* __restrict__ V, __half* __restrict__ O)
{
    __shared__ __half Ks[2][64][72];
    __shared__ __half Vs[2][64][72];

    const int t = threadIdx.x, lane = t & 31, wid = t >> 5;
    const int tb = blockIdx.x, h = blockIdx.y, b = blockIdx.z;
    const size_t base_q = ((size_t)(b * TT + tb * 128) * HH + h) * DKK;
    const size_t base_kv = ((size_t)(b * SS) * HH + h) * DKK;
    const int mw = wid * 16;

    // Stage Q (128x64) through Ks[0] (rows 0-63) and Vs[0] (rows 64-127),
    // extract A-fragments, then release the buffers for K/V.
#pragma unroll
    for (int i = 0; i < 2; i++) {
        const int id = t + i * 256;
        const int r = id >> 3, c8 = (id & 7) * 8;
        *(uint4*)&Ks[0][r][c8] = *(const uint4*)&Q[base_q + (size_t)r * HD + c8];
        *(uint4*)&Vs[0][r][c8] = *(const uint4*)&Q[base_q + (size_t)(64 + r) * HD + c8];
    }
    __syncthreads();
    unsigned qf[4][4];
    {
        __half (*Qsrc)[72] = (wid < 4) ? Ks[0] : Vs[0];
        const int qr = (mw & 63) + (lane & 15);
#pragma unroll
        for (int kk = 0; kk < 4; kk++)
            ldm_x4(sptr(&Qsrc[qr][kk * 16 + (lane >> 4) * 8]),
                   qf[kk][0], qf[kk][1], qf[kk][2], qf[kk][3]);
    }
    __syncthreads();

    auto load_kv = [&](int bufi, int sb) {
        const size_t off = base_kv + (size_t)(sb * 64) * HD;
#pragma unroll
        for (int i = 0; i < 2; i++) {
            const int id = t + i * 256;
            const int r = id >> 3, c8 = (id & 7) * 8;
            const size_t g = off + (size_t)r * HD + c8;
            CP16(sptr(&Ks[bufi][r][c8]), &K[g]);
            CP16(sptr(&Vs[bufi][r][c8]), &V[g]);
        }
    };

    load_kv(0, 0);
    CP_COMMIT();

    float o[8][4];
#pragma unroll
    for (int j = 0; j < 8; j++)
#pragma unroll
        for (int r = 0; r < 4; r++) o[j][r] = 0.0f;
    float m_lo = -1e30f, m_hi = -1e30f, l_lo = 0.0f, l_hi = 0.0f;

    const unsigned ones2 = 0x3C003C00u;
    unsigned onesb[2] = {ones2, ones2};

    for (int sb = 0; sb < SS / 64; sb++) {
        const int buf = sb & 1;
        CP_WAIT0();
        __syncthreads();
        if (sb + 1 < SS / 64) {
            load_kv(buf ^ 1, sb + 1);
            CP_COMMIT();
        }

        // S = Q @ K^T (log2 domain)
        float s[8][4];
#pragma unroll
        for (int j = 0; j < 8; j++)
#pragma unroll
            for (int r = 0; r < 4; r++) s[j][r] = 0.0f;
#pragma unroll
        for (int kk = 0; kk < 4; kk++) {
            unsigned bf[8][2];
#pragma unroll
            for (int np = 0; np < 4; np++) {
                unsigned r0, r1, r2, r3;
                const int nrow = np * 16 + (lane & 7) + ((lane >> 4) << 3);
                const int kcol = kk * 16 + ((lane >> 3) & 1) * 8;
                ldm_x4(sptr(&Ks[buf][nrow][kcol]), r0, r1, r2, r3);
                bf[2 * np][0] = r0; bf[2 * np][1] = r1;
                bf[2 * np + 1][0] = r2; bf[2 * np + 1][1] = r3;
            }
#pragma unroll
            for (int j = 0; j < 8; j++)
                mma16816(s[j], qf[kk], bf[j]);
        }

        // Online softmax (base 2)
        float mx_lo = -1e30f, mx_hi = -1e30f;
#pragma unroll
        for (int j = 0; j < 8; j++) {
            mx_lo = fmaxf(mx_lo, fmaxf(s[j][0], s[j][1]));
            mx_hi = fmaxf(mx_hi, fmaxf(s[j][2], s[j][3]));
        }
        mx_lo = fmaxf(mx_lo, __shfl_xor_sync(0xffffffffu, mx_lo, 1));
        mx_lo = fmaxf(mx_lo, __shfl_xor_sync(0xffffffffu, mx_lo, 2));
        mx_hi = fmaxf(mx_hi, __shfl_xor_sync(0xffffffffu, mx_hi, 1));
        mx_hi = fmaxf(mx_hi, __shfl_xor_sync(0xffffffffu, mx_hi, 2));

        const float mn_lo = fmaxf(m_lo, mx_lo);
        const float mn_hi = fmaxf(m_hi, mx_hi);
        const float a_lo = ex2f(m_lo - mn_lo);
        const float a_hi = ex2f(m_hi - mn_hi);
        m_lo = mn_lo; m_hi = mn_hi;
#pragma unroll
        for (int j = 0; j < 8; j++) {
            o[j][0] *= a_lo; o[j][1] *= a_lo;
            o[j][2] *= a_hi; o[j][3] *= a_hi;
        }

        // P = 2^(s-mn) as fp16 A-fragments; row sums via ones-MMA; O += P@V
        float sumf[4] = {0.0f, 0.0f, 0.0f, 0.0f};
#pragma unroll
        for (int kk = 0; kk < 4; kk++) {
            unsigned pa[4];
            pa[0] = ex2h2(pack2(s[2 * kk][0] - mn_lo, s[2 * kk][1] - mn_lo));
            pa[1] = ex2h2(pack2(s[2 * kk][2] - mn_hi, s[2 * kk][3] - mn_hi));
            pa[2] = ex2h2(pack2(s[2 * kk + 1][0] - mn_lo, s[2 * kk + 1][1] - mn_lo));
            pa[3] = ex2h2(pack2(s[2 * kk + 1][2] - mn_hi, s[2 * kk + 1][3] - mn_hi));
            mma16816(sumf, pa, onesb);

            unsigned vb[8][2];
#pragma unroll
            for (int np = 0; np < 4; np++) {
                unsigned r0, r1, r2, r3;
                ldm_x4_t(sptr(&Vs[buf][kk * 16 + (lane & 15)][np * 16 + (lane >> 4) * 8]),
                         r0, r1, r2, r3);
                vb[2 * np][0] = r0; vb[2 * np][1] = r1;
                vb[2 * np + 1][0] = r2; vb[2 * np + 1][1] = r3;
            }
#pragma unroll
            for (int j = 0; j < 8; j++)
                mma16816(o[j], pa, vb[j]);
        }
        l_lo = l_lo * a_lo + sumf[0];
        l_hi = l_hi * a_hi + sumf[2];
    }

    // Normalize + store fp16
    const float inv_lo = 1.0f / l_lo, inv_hi = 1.0f / l_hi;
    const int row_lo = mw + (lane >> 2);
    const int row_hi = row_lo + 8;
#pragma unroll
    for (int j = 0; j < 8; j++) {
        const int col = j * 8 + (lane & 3) * 2;
        *(__half2*)&O[base_q + (size_t)row_lo * HD + col] =
            __floats2half2_rn(o[j][0] * inv_lo, o[j][1] * inv_lo);
        *(__half2*)&O[base_q + (size_t)row_hi * HD + col] =
            __floats2half2_rn(o[j][2] * inv_hi, o[j][3] * inv_hi);
    }
}

// ---------------------------------------------------------------------------
// Launch
// ---------------------------------------------------------------------------
extern "C" void kernel_launch(void* const* d_in, const int* in_sizes, int n_in,
                              void* d_out, int out_size)
{
    const float* query = (const float*)d_in[0];
    const float* value = (const float*)d_in[1];
    const float* key   = (const float*)d_in[2];
    const float* Wq    = (const float*)d_in[3];
    const float* bq    = (const float*)d_in[4];
    const float* Wk    = (const float*)d_in[5];
    const float* bk    = (const float*)d_in[6];
    const float* Wv    = (const float*)d_in[7];
    const float* bv    = (const float*)d_in[8];
    const float* Wo    = (const float*)d_in[9];
    const float* bo    = (const float*)d_in[10];
    float* out = (float*)d_out;

    __half *xq, *xk, *xv, *wq, *wk, *wv, *wo, *q, *k, *v, *attn;
    cudaGetSymbolAddress((void**)&xq, g_xq);
    cudaGetSymbolAddress((void**)&xk, g_xk);
    cudaGetSymbolAddress((void**)&xv, g_xv);
    cudaGetSymbolAddress((void**)&wq, g_wq);
    cudaGetSymbolAddress((void**)&wk, g_wk);
    cudaGetSymbolAddress((void**)&wv, g_wv);
    cudaGetSymbolAddress((void**)&wo, g_wo);
    cudaGetSymbolAddress((void**)&q,  g_q);
    cudaGetSymbolAddress((void**)&k,  g_k);
    cudaGetSymbolAddress((void**)&v,  g_v);
    cudaGetSymbolAddress((void**)&attn, g_attn);

    // Conversions: inputs (4M each), weights (1M each)
    f2h_inputs<<<dim3(MROWS * DD / 2048, 3), 256>>>(query, key, value, xq, xk, xv);
    f2h_weights<<<dim3(DD * HD / 2048, 4), 256>>>(Wq, Wk, Wv, Wo, wq, wk, wv, wo);

    // Projections (batched), q scaled by (1/sqrt(DK)) * log2(e) for base-2 softmax
    ProjArgs p;
    p.A[0] = xq; p.A[1] = xk; p.A[2] = xv;
    p.W[0] = wq; p.W[1] = wk; p.W[2] = wv;
    p.bias[0] = bq; p.bias[1] = bk; p.bias[2] = bv;
    p.C[0] = q; p.C[1] = k; p.C[2] = v;
    p.scale[0] = 0.125f * 1.44269504088896f; p.scale[1] = 1.0f; p.scale[2] = 1.0f;
    proj_gemm<<<dim3(HD / 128, MROWS / 128, 3), 256>>>(p);

    flash_mma<<<dim3(TT / 128, HH, BB), 256>>>(q, k, v, attn);

    out_gemm<<<dim3(DD / 128, MROWS / 128), 256>>>(attn, wo, bo, out);
}